// round 12
// baseline (speedup 1.0000x reference)
#include <cuda_runtime.h>
#include <cuda_bf16.h>

// Problem constants (fixed by reference_code)
#define HH 768
#define WW 768
#define BB 9
#define CC 3
#define NS 100          // N_SAMPLES
#define MM 13           // offsets with dy^2+dx^2 <= 4
#define DD 27           // PATCH*PATCH*C
#define DP 28           // padded anchor stride: 7 float4, 16B-aligned
#define NPATCH (BB * MM)            // 117
#define NTHREADS 128                // 4 warps; thread p owns patch p (p < 117)
#define NARRIVE (NS * (NTHREADS / 32))   // 400 warp-level arrivals
// scale = (1/T^2) / (K * B * NS) = 4 / (8*9*100); divide by counts[n] per warp
#define BASE_SCALE (4.0f / (8.0f * 9.0f * 100.0f))

// Fixed-point packing: ONE u64 atomic per warp carries sum and counter.
//   low 55 bits:  sum of per-warp partials, each partial*2^44 rounded
//                 (400 partials, each < 0.06*2^44 < 2^40 -> total < 2^49)
//   high 9 bits:  arrival counter (reaches 400 < 512)
// Integer adds commute -> bit-deterministic; the last arriver's return value
// already contains the complete sum (no second atomic, no acquire re-read).
#define FIX_SCALE   1.7592186044416e13f      // 2^44
#define FIX_INV     5.684341886080802e-14    // 2^-44 (double)
#define CNT_ONE     (1ULL << 55)
#define SUM_MASK    ((1ULL << 55) - 1ULL)

// Nibble-packed offsets (value+2 per nibble), pure-ALU decode (no LDC):
// offy: -2,-1,-1,-1, 0, 0, 0, 0, 0, 1, 1, 1, 2
// offx:  0,-1, 0, 1,-2,-1, 0, 1, 2,-1, 0, 1, 0
#define OY_PACK 0x4333222221110ULL
#define OX_PACK 0x2321432103212ULL
#define OFFY(m) ((int)((OY_PACK >> (4 * (m))) & 15ULL) - 2)
#define OFFX(m) ((int)((OX_PACK >> (4 * (m))) & 15ULL) - 2)

__device__ unsigned long long g_pack = 0ULL;  // {counter:9 | fixed-point sum:55}

__global__ __launch_bounds__(NTHREADS)
void fused_kernel(const float* __restrict__ latents,
                  const int*   __restrict__ anchor_idx,
                  float*       __restrict__ out) {
    __shared__ __align__(16) float sa[BB * DP];   // 9 NORMALIZED anchor vectors

    const int tid  = threadIdx.x;
    const int n    = blockIdx.x;
    const int a    = __ldg(&anchor_idx[n]);
    const int ay   = a / WW;
    const int ax   = a - ay * WW;

    // --- Each thread owns one patch (j,m); gather 27 scattered LDG (MLP=27),
    //     normalize ENTIRELY in registers. Only anchors (m==6) go to shared.
    const bool active = (tid < NPATCH);
    const int  pp  = active ? tid : 0;
    const int  j   = pp / MM;
    const int  m   = pp - j * MM;

    int py = ay + OFFY(m);
    int px = ax + OFFX(m);
    const bool valid = (py >= 0 && py < HH && px >= 0 && px < WW);
    py = min(max(py, 0), HH - 1);              // matches jnp.clip on neighbor pos
    px = min(max(px, 0), WW - 1);

    // cnt = #valid offsets. Lanes 0..12 of EVERY warp hold 13 consecutive tids,
    // whose m values cover all residues mod 13 exactly once -> ballot+popc.
    const unsigned int bal = __ballot_sync(0xFFFFFFFFu, valid);
    const int cnt = __popc(bal & 0x1FFFu);

    float4 v4[7];
    {
        const float* base = latents + (size_t)j * (HH * WW * CC);
        float v[DD];
        float s0 = 0.0f, s1 = 0.0f, s2 = 0.0f;   // split accumulators: short chain
        #pragma unroll
        for (int ky = -1; ky <= 1; ky++) {
            const int yy = min(max(py + ky, 0), HH - 1);   // edge-pad clamp
            #pragma unroll
            for (int kx = -1; kx <= 1; kx++) {
                const int xx = min(max(px + kx, 0), WW - 1);
                const float* p = base + ((size_t)yy * WW + xx) * CC;
                const float f0 = __ldg(p + 0);
                const float f1 = __ldg(p + 1);
                const float f2 = __ldg(p + 2);
                const int o = ((ky + 1) * 3 + (kx + 1)) * 3;
                v[o + 0] = f0;  s0 = fmaf(f0, f0, s0);
                v[o + 1] = f1;  s1 = fmaf(f1, f1, s1);
                v[o + 2] = f2;  s2 = fmaf(f2, f2, s2);
            }
        }
        const float ss  = (s0 + s1) + s2;
        // rsqrtf(max(ss,1e-24)) == 1/max(sqrt(ss),1e-12): sqrt is monotone.
        const float inv = rsqrtf(fmaxf(ss, 1e-24f));
        #pragma unroll
        for (int q = 0; q < 6; q++)
            v4[q] = make_float4(v[4*q]*inv, v[4*q+1]*inv, v[4*q+2]*inv, v[4*q+3]*inv);
        v4[6] = make_float4(v[24]*inv, v[25]*inv, v[26]*inv, 0.0f);
    }

    // Publish the 9 anchor vectors (offset 6 == (0,0)) to shared.
    if (active && m == 6) {
        float4* dst = (float4*)&sa[j * DP];
        #pragma unroll
        for (int q = 0; q < 7; q++) dst[q] = v4[q];
    }
    __syncthreads();

    // --- Dot my register-resident patch against all 9 anchors (broadcast LDS,
    //     uniform address within the warp = 1 crossbar cycle per float4).
    const bool ok = active && valid;
    float acc = 0.0f;
    #pragma unroll
    for (int b = 0; b < BB; b++) {
        const float4* ar = (const float4*)&sa[b * DP];
        float d0 = 0.0f, d1 = 0.0f, d2 = 0.0f, d3 = 0.0f;
        #pragma unroll
        for (int q = 0; q < 7; q++) {
            const float4 a4 = ar[q];
            d0 = fmaf(a4.x, v4[q].x, d0);
            d1 = fmaf(a4.y, v4[q].y, d1);
            d2 = fmaf(a4.z, v4[q].z, d2);
            d3 = fmaf(a4.w, v4[q].w, d3);      // pad lane: 0*0
        }
        const float d = (d0 + d1) + (d2 + d3);
        const float wgt = (ok && j != b) ? 1.0f : 0.0f;
        acc = fmaf(d * d, wgt, acc);
    }

    // --- Warp reduction (deterministic tree), then ONE packed atomic per warp.
    //     No cross-warp smem reduce, no second __syncthreads, no serial tail.
    #pragma unroll
    for (int o = 16; o > 0; o >>= 1)
        acc += __shfl_down_sync(0xFFFFFFFFu, acc, o);

    if ((tid & 31) == 0) {
        const float partial = acc * (BASE_SCALE / (float)cnt);   // >= 0
        const unsigned long long q =
            (unsigned long long)__float2ll_rn(partial * FIX_SCALE);
        const unsigned long long prev = atomicAdd(&g_pack, CNT_ONE | q);
        if ((prev >> 55) == NARRIVE - 1) {     // 400th arriver owns the finish
            const unsigned long long total = (prev & SUM_MASK) + q;
            out[0] = (float)((double)total * FIX_INV);
            g_pack = 0ULL;                     // reset for next graph replay
        }
    }
}

extern "C" void kernel_launch(void* const* d_in, const int* in_sizes, int n_in,
                              void* d_out, int out_size) {
    const float* latents    = (const float*)d_in[0];
    const int*   anchor_idx = (const int*)d_in[1];
    float*       out        = (float*)d_out;

    fused_kernel<<<NS, NTHREADS>>>(latents, anchor_idx, out);
}

// round 13
// speedup vs baseline: 1.3592x; 1.3592x over previous
#include <cuda_runtime.h>
#include <cuda_bf16.h>

// Problem constants (fixed by reference_code)
#define HH 768
#define WW 768
#define BB 9
#define CC 3
#define NS 100          // N_SAMPLES
#define MM 13           // offsets with dy^2+dx^2 <= 4
#define DD 27           // PATCH*PATCH*C
#define DP 28           // padded anchor stride: 7 float4, 16B-aligned
#define NPATCH (BB * MM)            // 117
#define NTHREADS 128                // 4 warps; thread p owns patch p (p < 117)
// scale = (1/T^2) / (K * B * NS) = 4 / (8*9*100); divide by counts[n] per block
#define BASE_SCALE (4.0f / (8.0f * 9.0f * 100.0f))

// Fixed-point packing: ONE u64 atomic PER BLOCK carries sum and counter.
//   low 56 bits:  sum of per-anchor partials, each partial*2^44 rounded
//                 (100 partials, each < 0.06*2^44 < 2^40 -> total < 2^47)
//   high 8 bits:  arrival counter (reaches 100 < 256)
// Integer adds commute -> bit-deterministic; the last arriver's return value
// already contains the complete sum (no second atomic, no acquire re-read).
// NOTE (R11 post-mortem): one atomic per WARP (400 same-address u64 atomics)
// serialized ~32cy each at the LTS atomic ALU and cost ~2.4us. Keep it at 100.
#define FIX_SCALE   1.7592186044416e13f      // 2^44
#define FIX_INV     5.684341886080802e-14    // 2^-44 (double)
#define CNT_ONE     (1ULL << 56)
#define SUM_MASK    ((1ULL << 56) - 1ULL)

// Nibble-packed offsets (value+2 per nibble), pure-ALU decode (no LDC):
// offy: -2,-1,-1,-1, 0, 0, 0, 0, 0, 1, 1, 1, 2
// offx:  0,-1, 0, 1,-2,-1, 0, 1, 2,-1, 0, 1, 0
#define OY_PACK 0x4333222221110ULL
#define OX_PACK 0x2321432103212ULL
#define OFFY(m) ((int)((OY_PACK >> (4 * (m))) & 15ULL) - 2)
#define OFFX(m) ((int)((OX_PACK >> (4 * (m))) & 15ULL) - 2)

__device__ unsigned long long g_pack = 0ULL;  // {counter:8 | fixed-point sum:56}

__global__ __launch_bounds__(NTHREADS)
void fused_kernel(const float* __restrict__ latents,
                  const int*   __restrict__ anchor_idx,
                  float*       __restrict__ out) {
    __shared__ __align__(16) float sa[BB * DP];   // 9 NORMALIZED anchor vectors
    __shared__ float s_wsum[NTHREADS / 32];

    const int tid  = threadIdx.x;
    const int n    = blockIdx.x;
    const int a    = __ldg(&anchor_idx[n]);
    const int ay   = a / WW;
    const int ax   = a - ay * WW;

    // --- Each thread owns one patch (j,m); gather 27 scattered LDG (MLP=27),
    //     normalize ENTIRELY in registers. Only anchors (m==6) go to shared.
    const bool active = (tid < NPATCH);
    const int  pp  = active ? tid : 0;
    const int  j   = pp / MM;
    const int  m   = pp - j * MM;

    int py = ay + OFFY(m);
    int px = ax + OFFX(m);
    const bool valid = (py >= 0 && py < HH && px >= 0 && px < WW);
    py = min(max(py, 0), HH - 1);              // matches jnp.clip on neighbor pos
    px = min(max(px, 0), WW - 1);

    // cnt = #valid offsets. Lanes 0..12 of warp 0 hold patches (j=0, m=0..12),
    // and validity depends only on m -> ballot+popc replaces a serial loop.
    const unsigned int bal = __ballot_sync(0xFFFFFFFFu, valid);
    const int cnt = __popc(bal & 0x1FFFu);

    float4 v4[7];
    {
        const float* base = latents + (size_t)j * (HH * WW * CC);
        float v[DD];
        float s0 = 0.0f, s1 = 0.0f, s2 = 0.0f;   // split accumulators: short chain
        #pragma unroll
        for (int ky = -1; ky <= 1; ky++) {
            const int yy = min(max(py + ky, 0), HH - 1);   // edge-pad clamp
            #pragma unroll
            for (int kx = -1; kx <= 1; kx++) {
                const int xx = min(max(px + kx, 0), WW - 1);
                const float* p = base + ((size_t)yy * WW + xx) * CC;
                const float f0 = __ldg(p + 0);
                const float f1 = __ldg(p + 1);
                const float f2 = __ldg(p + 2);
                const int o = ((ky + 1) * 3 + (kx + 1)) * 3;
                v[o + 0] = f0;  s0 = fmaf(f0, f0, s0);
                v[o + 1] = f1;  s1 = fmaf(f1, f1, s1);
                v[o + 2] = f2;  s2 = fmaf(f2, f2, s2);
            }
        }
        const float ss  = (s0 + s1) + s2;
        // rsqrtf(max(ss,1e-24)) == 1/max(sqrt(ss),1e-12): sqrt is monotone.
        const float inv = rsqrtf(fmaxf(ss, 1e-24f));
        #pragma unroll
        for (int q = 0; q < 6; q++)
            v4[q] = make_float4(v[4*q]*inv, v[4*q+1]*inv, v[4*q+2]*inv, v[4*q+3]*inv);
        v4[6] = make_float4(v[24]*inv, v[25]*inv, v[26]*inv, 0.0f);
    }

    // Publish the 9 anchor vectors (offset 6 == (0,0)) to shared.
    if (active && m == 6) {
        float4* dst = (float4*)&sa[j * DP];
        #pragma unroll
        for (int q = 0; q < 7; q++) dst[q] = v4[q];
    }
    __syncthreads();

    // --- Dot my register-resident patch against all 9 anchors (broadcast LDS,
    //     uniform address within the warp = 1 crossbar cycle per float4).
    const bool ok = active && valid;
    float acc = 0.0f;
    #pragma unroll
    for (int b = 0; b < BB; b++) {
        const float4* ar = (const float4*)&sa[b * DP];
        float d0 = 0.0f, d1 = 0.0f, d2 = 0.0f, d3 = 0.0f;
        #pragma unroll
        for (int q = 0; q < 7; q++) {
            const float4 a4 = ar[q];
            d0 = fmaf(a4.x, v4[q].x, d0);
            d1 = fmaf(a4.y, v4[q].y, d1);
            d2 = fmaf(a4.z, v4[q].z, d2);
            d3 = fmaf(a4.w, v4[q].w, d3);      // pad lane: 0*0
        }
        const float d = (d0 + d1) + (d2 + d3);
        if (ok && j != b) acc += d * d;
    }

    // --- Block reduction (deterministic tree over 4 warps) ---
    #pragma unroll
    for (int o = 16; o > 0; o >>= 1)
        acc += __shfl_down_sync(0xFFFFFFFFu, acc, o);
    if ((tid & 31) == 0) s_wsum[tid >> 5] = acc;
    __syncthreads();

    // --- Tail: ONE packed relaxed atomic per block. The 100th arriver's
    //     return value carries the full sum; it converts, writes, resets.
    if (tid == 0) {
        float s = 0.0f;
        #pragma unroll
        for (int k = 0; k < NTHREADS / 32; k++) s += s_wsum[k];
        const float partial = s * (BASE_SCALE / (float)cnt);   // >= 0, < 0.06
        const unsigned long long q =
            (unsigned long long)__float2ll_rn(partial * FIX_SCALE);
        const unsigned long long prev = atomicAdd(&g_pack, CNT_ONE | q);
        if ((prev >> 56) == NS - 1) {          // 100th arriver owns the finish
            const unsigned long long total = (prev & SUM_MASK) + q;
            out[0] = (float)((double)total * FIX_INV);
            g_pack = 0ULL;                     // reset for next graph replay
        }
    }
}

extern "C" void kernel_launch(void* const* d_in, const int* in_sizes, int n_in,
                              void* d_out, int out_size) {
    const float* latents    = (const float*)d_in[0];
    const int*   anchor_idx = (const int*)d_in[1];
    float*       out        = (float*)d_out;

    fused_kernel<<<NS, NTHREADS>>>(latents, anchor_idx, out);
}